// round 1
// baseline (speedup 1.0000x reference)
#include <cuda_runtime.h>
#include <cuda_bf16.h>
#include <math.h>

#define N_NODES 131072
#define N_EDGES 524288
#define H_DIM   128
#define K_SEL   (N_NODES / 2)
#define LN_EPS  1e-5f

// ---------------- scratch (static device globals: no allocations allowed) ----------------
__device__ float    g_B0[(size_t)N_NODES * H_DIM];
__device__ float    g_B1[(size_t)N_NODES * H_DIM];
__device__ float    g_B2[(size_t)N_NODES * H_DIM];
__device__ float    g_score[N_NODES];
__device__ unsigned g_key[N_NODES];
__device__ int      g_mask[N_NODES];
__device__ int      g_map[N_NODES];
__device__ unsigned g_hist[256];
__device__ unsigned g_prefix;
__device__ unsigned g_rem;
__device__ int      g_cnt;
__device__ unsigned g_blkeq[256];
__device__ unsigned g_blkoff[256];
__device__ float    g_invnorm;

// ---------------- helpers ----------------
__device__ __forceinline__ unsigned sortable_key(float f) {
    unsigned u = __float_as_uint(f);
    return (u & 0x80000000u) ? ~u : (u | 0x80000000u);
}
__device__ __forceinline__ float gelu_exact(float x) {
    return x * normcdff(x);   // x * 0.5*(1+erf(x/sqrt(2)))
}

// ---------------- pool_p norm ----------------
__global__ void k_norm(const float* __restrict__ p) {
    __shared__ float s[128];
    int t = threadIdx.x;
    float v = p[t];
    s[t] = v * v;
    __syncthreads();
    for (int off = 64; off > 0; off >>= 1) {
        if (t < off) s[t] += s[t + off];
        __syncthreads();
    }
    if (t == 0) g_invnorm = rsqrtf(s[0]);
}

// ---------------- scores + keys (warp per row) ----------------
__global__ void k_score(const float* __restrict__ x, const float* __restrict__ p) {
    int row  = blockIdx.x * 4 + (threadIdx.x >> 5);
    int lane = threadIdx.x & 31;
    int c = lane * 4;
    float4 xv = *(const float4*)(x + (size_t)row * H_DIM + c);
    float4 pv = *(const float4*)(p + c);
    float v = xv.x * pv.x + xv.y * pv.y + xv.z * pv.z + xv.w * pv.w;
    #pragma unroll
    for (int off = 16; off > 0; off >>= 1) v += __shfl_xor_sync(0xffffffffu, v, off);
    if (lane == 0) {
        float s = v * g_invnorm;
        g_score[row] = s;
        g_key[row] = sortable_key(s);
    }
}

// ---------------- radix select of k-th largest key ----------------
__global__ void k_rinit() {
    int t = threadIdx.x;
    g_hist[t] = 0;
    if (t == 0) { g_prefix = 0; g_rem = K_SEL; g_cnt = 0; }
}
__global__ void k_hist(int shift) {
    __shared__ unsigned h[256];
    int t = threadIdx.x;
    h[t] = 0;
    __syncthreads();
    unsigned pref = g_prefix;
    unsigned hi = (shift == 24) ? 0u : (0xFFFFFFFFu << (shift + 8));
    for (int i = blockIdx.x * blockDim.x + t; i < N_NODES; i += gridDim.x * blockDim.x) {
        unsigned u = g_key[i];
        if ((u & hi) == pref) atomicAdd(&h[(u >> shift) & 255u], 1u);
    }
    __syncthreads();
    if (h[t]) atomicAdd(&g_hist[t], h[t]);
}
__global__ void k_rselect(int shift) {
    unsigned rem = g_rem, pref = g_prefix;
    for (int b = 255; b >= 0; b--) {
        unsigned c = g_hist[b];
        if (c < rem) rem -= c;
        else { pref |= ((unsigned)b) << shift; break; }
    }
    g_prefix = pref;
    g_rem = rem;
    for (int i = 0; i < 256; i++) g_hist[i] = 0;
}

// ---------------- tie-aware selection (lowest index among equals, matching lax.top_k) ----
__global__ void k_eqcount() {
    __shared__ unsigned cnt;
    int t = threadIdx.x;
    if (t == 0) cnt = 0;
    __syncthreads();
    int i = blockIdx.x * 512 + t;
    unsigned T = g_prefix;
    if (g_key[i] == T) atomicAdd(&cnt, 1u);
    __syncthreads();
    if (t == 0) g_blkeq[blockIdx.x] = cnt;
}
__global__ void k_eqscan() {
    unsigned run = 0;
    for (int i = 0; i < 256; i++) { g_blkoff[i] = run; run += g_blkeq[i]; }
}
__global__ void k_mark() {
    __shared__ int sb[512];
    int t = threadIdx.x;
    int i = blockIdx.x * 512 + t;
    unsigned T = g_prefix;
    unsigned u = g_key[i];
    int eq = (u == T) ? 1 : 0;
    int gt = (u > T) ? 1 : 0;
    sb[t] = eq;
    __syncthreads();
    for (int off = 1; off < 512; off <<= 1) {
        int v = (t >= off) ? sb[t - off] : 0;
        __syncthreads();
        sb[t] += v;
        __syncthreads();
    }
    int excl = sb[t] - eq;
    int sel = gt || (eq && (g_blkoff[blockIdx.x] + (unsigned)excl) < g_rem);
    if (sel) {
        g_mask[i] = 1;
        g_map[i] = atomicAdd(&g_cnt, 1);
    } else {
        g_mask[i] = 0;
        g_map[i] = 0;
    }
}

// ---------------- gather selected rows, scale by tanh(score) ----------------
__global__ void k_xp(const float* __restrict__ x, float* __restrict__ xp) {
    int wid  = blockIdx.x * 8 + (threadIdx.x >> 5);
    int lane = threadIdx.x & 31;
    if (!g_mask[wid]) return;
    float t = tanhf(g_score[wid]);
    int c = lane * 4;
    float4 v = *(const float4*)(x + (size_t)wid * H_DIM + c);
    v.x *= t; v.y *= t; v.z *= t; v.w *= t;
    *(float4*)(xp + (size_t)g_map[wid] * H_DIM + c) = v;
}

// ---------------- zero ----------------
__global__ void k_zero(float4* __restrict__ p, int n4) {
    for (int i = blockIdx.x * blockDim.x + threadIdx.x; i < n4; i += gridDim.x * blockDim.x)
        p[i] = make_float4(0.f, 0.f, 0.f, 0.f);
}

// ---------------- down-conv edge scatter (warp per edge) ----------------
__global__ void k_down_edges(const int* __restrict__ senders, const int* __restrict__ receivers,
                             const float* __restrict__ xp, float* __restrict__ agg) {
    int e    = blockIdx.x * 8 + (threadIdx.x >> 5);
    int lane = threadIdx.x & 31;
    int s = senders[e], r = receivers[e];
    if (!(g_mask[s] & g_mask[r])) return;
    int ms = g_map[s], mr = g_map[r];
    int c = lane * 4;
    float4 vs = *(const float4*)(xp + (size_t)ms * H_DIM + c);
    float4 vr = *(const float4*)(xp + (size_t)mr * H_DIM + c);
    float* dr = agg + (size_t)mr * H_DIM + c;
    float* ds = agg + (size_t)ms * H_DIM + c;
    atomicAdd(dr + 0, vs.x); atomicAdd(dr + 1, vs.y); atomicAdd(dr + 2, vs.z); atomicAdd(dr + 3, vs.w);
    atomicAdd(ds + 0, vr.x); atomicAdd(ds + 1, vr.y); atomicAdd(ds + 2, vr.z); atomicAdd(ds + 3, vr.w);
}

// ---------------- up-conv edge scatter ----------------
__global__ void k_up_edges(const int* __restrict__ senders, const int* __restrict__ receivers,
                           const float* __restrict__ x, const float* __restrict__ xd,
                           float* __restrict__ agg_skip, float* __restrict__ agg_rec) {
    int e    = blockIdx.x * 8 + (threadIdx.x >> 5);
    int lane = threadIdx.x & 31;
    int s = senders[e], r = receivers[e];
    int c = lane * 4;
    float4 vs = *(const float4*)(x + (size_t)s * H_DIM + c);
    float4 vr = *(const float4*)(x + (size_t)r * H_DIM + c);
    float* pr = agg_skip + (size_t)r * H_DIM + c;
    float* ps = agg_skip + (size_t)s * H_DIM + c;
    atomicAdd(pr + 0, vs.x); atomicAdd(pr + 1, vs.y); atomicAdd(pr + 2, vs.z); atomicAdd(pr + 3, vs.w);
    atomicAdd(ps + 0, vr.x); atomicAdd(ps + 1, vr.y); atomicAdd(ps + 2, vr.z); atomicAdd(ps + 3, vr.w);
    if (g_mask[s]) {
        float4 v = *(const float4*)(xd + (size_t)g_map[s] * H_DIM + c);
        float* d = agg_rec + (size_t)r * H_DIM + c;
        atomicAdd(d + 0, v.x); atomicAdd(d + 1, v.y); atomicAdd(d + 2, v.z); atomicAdd(d + 3, v.w);
    }
    if (g_mask[r]) {
        float4 v = *(const float4*)(xd + (size_t)g_map[r] * H_DIM + c);
        float* d = agg_rec + (size_t)s * H_DIM + c;
        atomicAdd(d + 0, v.x); atomicAdd(d + 1, v.y); atomicAdd(d + 2, v.z); atomicAdd(d + 3, v.w);
    }
}

// ---------------- fused GEMM (+bias, +GELU or +LN epilogue) ----------------
// OUT[rows,128] = epi( A@W(+A2@W2) + bias ). Block: 256 thr, 64-row x 128-col tile.
// Thread tile: 8 rows x 4 cols. W resident in dynamic SMEM.
template<bool TWO_IN, bool DO_LN>
__global__ __launch_bounds__(256) void gemm_kernel(
    const float* __restrict__ A, const float* __restrict__ A2,
    const float* __restrict__ W, const float* __restrict__ bias,
    const float* __restrict__ gamma, const float* __restrict__ beta,
    float* __restrict__ out)
{
    extern __shared__ float sm[];
    constexpr int WROWS = TWO_IN ? 256 : 128;
    float* Ws = sm;
    float* As = sm + WROWS * 128;
    int tid = threadIdx.x;
    for (int i = tid * 4; i < WROWS * 128; i += 1024)
        *(float4*)(Ws + i) = *(const float4*)(W + i);
    int tx = tid & 31, ty = tid >> 5;
    size_t rowBase = (size_t)blockIdx.x * 64;

    float acc[8][4];
    float4 bv = *(const float4*)(bias + tx * 4);
    #pragma unroll
    for (int r = 0; r < 8; r++) { acc[r][0] = bv.x; acc[r][1] = bv.y; acc[r][2] = bv.z; acc[r][3] = bv.w; }

    #pragma unroll
    for (int pass = 0; pass < (TWO_IN ? 2 : 1); pass++) {
        const float* Ain = pass ? A2 : A;
        const float* Wp  = Ws + pass * 128 * 128;
        __syncthreads();
        for (int i = tid * 4; i < 64 * 128; i += 1024)
            *(float4*)(As + i) = *(const float4*)(Ain + rowBase * 128 + i);
        __syncthreads();
        #pragma unroll 4
        for (int k = 0; k < 128; k++) {
            float4 w = *(const float4*)(Wp + k * 128 + tx * 4);
            #pragma unroll
            for (int r = 0; r < 8; r++) {
                float a = As[(ty * 8 + r) * 128 + k];
                acc[r][0] += a * w.x; acc[r][1] += a * w.y;
                acc[r][2] += a * w.z; acc[r][3] += a * w.w;
            }
        }
    }

    if (!DO_LN) {
        #pragma unroll
        for (int r = 0; r < 8; r++) {
            size_t row = rowBase + ty * 8 + r;
            float4 o;
            o.x = gelu_exact(acc[r][0]); o.y = gelu_exact(acc[r][1]);
            o.z = gelu_exact(acc[r][2]); o.w = gelu_exact(acc[r][3]);
            *(float4*)(out + row * 128 + tx * 4) = o;
        }
    } else {
        float4 g4 = *(const float4*)(gamma + tx * 4);
        float4 b4 = *(const float4*)(beta + tx * 4);
        #pragma unroll
        for (int r = 0; r < 8; r++) {
            float s1 = acc[r][0] + acc[r][1] + acc[r][2] + acc[r][3];
            float s2 = acc[r][0]*acc[r][0] + acc[r][1]*acc[r][1]
                     + acc[r][2]*acc[r][2] + acc[r][3]*acc[r][3];
            #pragma unroll
            for (int off = 16; off > 0; off >>= 1) {
                s1 += __shfl_xor_sync(0xffffffffu, s1, off);
                s2 += __shfl_xor_sync(0xffffffffu, s2, off);
            }
            float mu = s1 * (1.0f / 128.0f);
            float var = s2 * (1.0f / 128.0f) - mu * mu;
            float rstd = rsqrtf(var + LN_EPS);
            size_t row = rowBase + ty * 8 + r;
            float4 o;
            o.x = (acc[r][0] - mu) * rstd * g4.x + b4.x;
            o.y = (acc[r][1] - mu) * rstd * g4.y + b4.y;
            o.z = (acc[r][2] - mu) * rstd * g4.z + b4.z;
            o.w = (acc[r][3] - mu) * rstd * g4.w + b4.w;
            *(float4*)(out + row * 128 + tx * 4) = o;
        }
    }
}

// ---------------- launch ----------------
extern "C" void kernel_launch(void* const* d_in, const int* in_sizes, int n_in,
                              void* d_out, int out_size) {
    const float* x      = (const float*)d_in[0];
    const int*   ei     = (const int*)d_in[1];
    const float* pool_p = (const float*)d_in[2];
    const float* dW1 = (const float*)d_in[3];
    const float* db1 = (const float*)d_in[4];
    const float* dW2 = (const float*)d_in[5];
    const float* db2 = (const float*)d_in[6];
    const float* dW3 = (const float*)d_in[7];
    const float* db3 = (const float*)d_in[8];
    const float* dg    = (const float*)d_in[9];
    const float* dbeta = (const float*)d_in[10];
    const float* uW1 = (const float*)d_in[11];
    const float* ub1 = (const float*)d_in[12];
    const float* uW2 = (const float*)d_in[13];
    const float* ub2 = (const float*)d_in[14];
    const float* uW3 = (const float*)d_in[15];
    const float* ub3 = (const float*)d_in[16];
    const float* ug    = (const float*)d_in[17];
    const float* ubeta = (const float*)d_in[18];
    float* out = (float*)d_out;

    const int* senders   = ei;
    const int* receivers = ei + N_EDGES;

    float *B0, *B1, *B2;
    cudaGetSymbolAddress((void**)&B0, g_B0);
    cudaGetSymbolAddress((void**)&B1, g_B1);
    cudaGetSymbolAddress((void**)&B2, g_B2);

    cudaFuncSetAttribute(gemm_kernel<false, false>, cudaFuncAttributeMaxDynamicSharedMemorySize, 98304);
    cudaFuncSetAttribute(gemm_kernel<false, true >, cudaFuncAttributeMaxDynamicSharedMemorySize, 98304);
    cudaFuncSetAttribute(gemm_kernel<true,  false>, cudaFuncAttributeMaxDynamicSharedMemorySize, 163840);

    // --- pooling scores + exact top-k selection ---
    k_norm<<<1, 128>>>(pool_p);
    k_score<<<N_NODES / 4, 128>>>(x, pool_p);
    k_rinit<<<1, 256>>>();
    for (int sh = 24; sh >= 0; sh -= 8) {
        k_hist<<<256, 256>>>(sh);
        k_rselect<<<1, 1>>>(sh);
    }
    k_eqcount<<<256, 512>>>();
    k_eqscan<<<1, 1>>>();
    k_mark<<<256, 512>>>();

    // --- x_p = x[sel] * tanh(score) -> B0 ---
    k_xp<<<N_NODES / 8, 256>>>(x, B0);

    // --- down conv: agg -> B1 ---
    k_zero<<<4096, 256>>>((float4*)B1, K_SEL * H_DIM / 4);
    k_down_edges<<<N_EDGES / 8, 256>>>(senders, receivers, B0, B1);
    gemm_kernel<false, false><<<K_SEL / 64, 256, 98304>>>(B1, nullptr, dW1, db1, nullptr, nullptr, B2);
    gemm_kernel<false, false><<<K_SEL / 64, 256, 98304>>>(B2, nullptr, dW2, db2, nullptr, nullptr, B1);
    gemm_kernel<false, true ><<<K_SEL / 64, 256, 98304>>>(B1, nullptr, dW3, db3, dg, dbeta, B0); // x_d -> B0

    // --- up conv: agg_skip -> B1, agg_rec -> B2 ---
    k_zero<<<8192, 256>>>((float4*)B1, N_NODES * H_DIM / 4);
    k_zero<<<8192, 256>>>((float4*)B2, N_NODES * H_DIM / 4);
    k_up_edges<<<N_EDGES / 8, 256>>>(senders, receivers, x, B0, B1, B2);
    // u1 = gelu(agg_rec@uW1[0:128] + agg_skip@uW1[128:256] + ub1) -> B0
    gemm_kernel<true,  false><<<N_NODES / 64, 256, 163840>>>(B2, B1, uW1, ub1, nullptr, nullptr, B0);
    gemm_kernel<false, false><<<N_NODES / 64, 256, 98304>>>(B0, nullptr, uW2, ub2, nullptr, nullptr, B1);
    gemm_kernel<false, true ><<<N_NODES / 64, 256, 98304>>>(B1, nullptr, uW3, ub3, ug, ubeta, out);
}

// round 2
// speedup vs baseline: 1.4071x; 1.4071x over previous
#include <cuda_runtime.h>
#include <cuda_bf16.h>
#include <math.h>

#define N_NODES 131072
#define N_EDGES 524288
#define H_DIM   128
#define K_SEL   (N_NODES / 2)
#define LN_EPS  1e-5f

// ---------------- scratch (static device globals: no allocations allowed) ----------------
__device__ float    g_B0[(size_t)N_NODES * H_DIM];
__device__ float    g_B1[(size_t)N_NODES * H_DIM];
__device__ float    g_B2[(size_t)N_NODES * H_DIM];
__device__ float    g_score[N_NODES];
__device__ float    g_ts[N_NODES];
__device__ unsigned g_key[N_NODES];
__device__ int      g_mapm[N_NODES];     // >=0: compact index if selected, -1 otherwise
__device__ unsigned g_hist[256];
__device__ unsigned g_prefix;
__device__ unsigned g_rem;
__device__ int      g_cnt;
__device__ unsigned g_blkeq[256];
__device__ unsigned g_blkoff[256];
__device__ float    g_invnorm;
// CSR of symmetrized graph
__device__ int      g_deg[N_NODES];
__device__ int      g_rowptr[N_NODES + 1];
__device__ int      g_cur[N_NODES];
__device__ int      g_adj[2 * N_EDGES];
__device__ int      g_tmpscan[N_NODES];
__device__ int      g_bsum[256];

// ---------------- helpers ----------------
__device__ __forceinline__ unsigned sortable_key(float f) {
    unsigned u = __float_as_uint(f);
    return (u & 0x80000000u) ? ~u : (u | 0x80000000u);
}
__device__ __forceinline__ float gelu_exact(float x) {
    return x * normcdff(x);
}

// ---------------- pool_p norm ----------------
__global__ void k_norm(const float* __restrict__ p) {
    __shared__ float s[128];
    int t = threadIdx.x;
    float v = p[t];
    s[t] = v * v;
    __syncthreads();
    for (int off = 64; off > 0; off >>= 1) {
        if (t < off) s[t] += s[t + off];
        __syncthreads();
    }
    if (t == 0) g_invnorm = rsqrtf(s[0]);
}

// ---------------- scores + keys (warp per row) ----------------
__global__ void k_score(const float* __restrict__ x, const float* __restrict__ p) {
    int row  = blockIdx.x * 4 + (threadIdx.x >> 5);
    int lane = threadIdx.x & 31;
    int c = lane * 4;
    float4 xv = *(const float4*)(x + (size_t)row * H_DIM + c);
    float4 pv = *(const float4*)(p + c);
    float v = xv.x * pv.x + xv.y * pv.y + xv.z * pv.z + xv.w * pv.w;
    #pragma unroll
    for (int off = 16; off > 0; off >>= 1) v += __shfl_xor_sync(0xffffffffu, v, off);
    if (lane == 0) {
        float s = v * g_invnorm;
        g_score[row] = s;
        g_ts[row] = tanhf(s);
        g_key[row] = sortable_key(s);
    }
}

// ---------------- radix select of k-th largest key ----------------
__global__ void k_rinit() {
    int t = threadIdx.x;
    g_hist[t] = 0;
    if (t == 0) { g_prefix = 0; g_rem = K_SEL; g_cnt = 0; }
}
__global__ void k_hist(int shift) {
    __shared__ unsigned h[256];
    int t = threadIdx.x;
    h[t] = 0;
    __syncthreads();
    unsigned pref = g_prefix;
    unsigned hi = (shift == 24) ? 0u : (0xFFFFFFFFu << (shift + 8));
    for (int i = blockIdx.x * blockDim.x + t; i < N_NODES; i += gridDim.x * blockDim.x) {
        unsigned u = g_key[i];
        if ((u & hi) == pref) atomicAdd(&h[(u >> shift) & 255u], 1u);
    }
    __syncthreads();
    if (h[t]) atomicAdd(&g_hist[t], h[t]);
}
__global__ void k_rselect(int shift) {
    unsigned rem = g_rem, pref = g_prefix;
    for (int b = 255; b >= 0; b--) {
        unsigned c = g_hist[b];
        if (c < rem) rem -= c;
        else { pref |= ((unsigned)b) << shift; break; }
    }
    g_prefix = pref;
    g_rem = rem;
    for (int i = 0; i < 256; i++) g_hist[i] = 0;
}

// ---------------- tie-aware selection ----------------
__global__ void k_eqcount() {
    __shared__ unsigned cnt;
    int t = threadIdx.x;
    if (t == 0) cnt = 0;
    __syncthreads();
    int i = blockIdx.x * 512 + t;
    unsigned T = g_prefix;
    if (g_key[i] == T) atomicAdd(&cnt, 1u);
    __syncthreads();
    if (t == 0) g_blkeq[blockIdx.x] = cnt;
}
__global__ void k_eqscan() {
    unsigned run = 0;
    for (int i = 0; i < 256; i++) { g_blkoff[i] = run; run += g_blkeq[i]; }
}
__global__ void k_mark() {
    __shared__ int sb[512];
    int t = threadIdx.x;
    int i = blockIdx.x * 512 + t;
    unsigned T = g_prefix;
    unsigned u = g_key[i];
    int eq = (u == T) ? 1 : 0;
    int gt = (u > T) ? 1 : 0;
    sb[t] = eq;
    __syncthreads();
    for (int off = 1; off < 512; off <<= 1) {
        int v = (t >= off) ? sb[t - off] : 0;
        __syncthreads();
        sb[t] += v;
        __syncthreads();
    }
    int excl = sb[t] - eq;
    int sel = gt || (eq && (g_blkoff[blockIdx.x] + (unsigned)excl) < g_rem);
    g_mapm[i] = sel ? atomicAdd(&g_cnt, 1) : -1;
}

// ---------------- CSR build ----------------
__global__ void k_count(const int* __restrict__ senders, const int* __restrict__ receivers) {
    for (int e = blockIdx.x * blockDim.x + threadIdx.x; e < N_EDGES; e += gridDim.x * blockDim.x) {
        atomicAdd(&g_deg[senders[e]], 1);
        atomicAdd(&g_deg[receivers[e]], 1);
    }
}
__global__ void k_scan1() {
    __shared__ int sb[512];
    int t = threadIdx.x;
    int i = blockIdx.x * 512 + t;
    int v = g_deg[i];
    sb[t] = v;
    __syncthreads();
    for (int off = 1; off < 512; off <<= 1) {
        int a = (t >= off) ? sb[t - off] : 0;
        __syncthreads();
        sb[t] += a;
        __syncthreads();
    }
    g_tmpscan[i] = sb[t];
    if (t == 511) g_bsum[blockIdx.x] = sb[511];
}
__global__ void k_scan2() {
    __shared__ int sb[256];
    int t = threadIdx.x;
    sb[t] = g_bsum[t];
    __syncthreads();
    for (int off = 1; off < 256; off <<= 1) {
        int a = (t >= off) ? sb[t - off] : 0;
        __syncthreads();
        sb[t] += a;
        __syncthreads();
    }
    g_bsum[t] = sb[t];
}
__global__ void k_scan3() {
    int t = threadIdx.x;
    int i = blockIdx.x * 512 + t;
    int off = (blockIdx.x > 0) ? g_bsum[blockIdx.x - 1] : 0;
    int incl = g_tmpscan[i] + off;
    int excl = incl - g_deg[i];
    g_rowptr[i] = excl;
    g_cur[i] = excl;
    if (i == N_NODES - 1) g_rowptr[N_NODES] = incl;
}
__global__ void k_scatter(const int* __restrict__ senders, const int* __restrict__ receivers) {
    for (int e = blockIdx.x * blockDim.x + threadIdx.x; e < N_EDGES; e += gridDim.x * blockDim.x) {
        int s = senders[e], r = receivers[e];
        g_adj[atomicAdd(&g_cur[s], 1)] = r;
        g_adj[atomicAdd(&g_cur[r], 1)] = s;
    }
}

// ---------------- down aggregation: gather (warp per node) ----------------
__global__ void k_down_gather(const float* __restrict__ x, float* __restrict__ out) {
    int v    = blockIdx.x * 8 + (threadIdx.x >> 5);
    int lane = threadIdx.x & 31;
    int mv = g_mapm[v];
    if (mv < 0) return;
    int c = lane * 4;
    int beg = g_rowptr[v], end = g_rowptr[v + 1];
    float4 acc = make_float4(0.f, 0.f, 0.f, 0.f);
    for (int i = beg; i < end; i++) {
        int u = g_adj[i];
        if (g_mapm[u] >= 0) {
            float t = g_ts[u];
            float4 xv = *(const float4*)(x + (size_t)u * H_DIM + c);
            acc.x += xv.x * t; acc.y += xv.y * t;
            acc.z += xv.z * t; acc.w += xv.w * t;
        }
    }
    *(float4*)(out + (size_t)mv * H_DIM + c) = acc;
}

// ---------------- up aggregation: gather (warp per node) ----------------
__global__ void k_up_gather(const float* __restrict__ x, const float* __restrict__ xd,
                            float* __restrict__ agg_skip, float* __restrict__ agg_rec) {
    int v    = blockIdx.x * 8 + (threadIdx.x >> 5);
    int lane = threadIdx.x & 31;
    int c = lane * 4;
    int beg = g_rowptr[v], end = g_rowptr[v + 1];
    float4 as = make_float4(0.f, 0.f, 0.f, 0.f);
    float4 ar = make_float4(0.f, 0.f, 0.f, 0.f);
    for (int i = beg; i < end; i++) {
        int u = g_adj[i];
        float4 xv = *(const float4*)(x + (size_t)u * H_DIM + c);
        as.x += xv.x; as.y += xv.y; as.z += xv.z; as.w += xv.w;
        int mu = g_mapm[u];
        if (mu >= 0) {
            float4 dv = *(const float4*)(xd + (size_t)mu * H_DIM + c);
            ar.x += dv.x; ar.y += dv.y; ar.z += dv.z; ar.w += dv.w;
        }
    }
    *(float4*)(agg_skip + (size_t)v * H_DIM + c) = as;
    *(float4*)(agg_rec  + (size_t)v * H_DIM + c) = ar;
}

// ---------------- fused GEMM (+bias, +GELU or +LN epilogue) ----------------
template<bool TWO_IN, bool DO_LN>
__global__ __launch_bounds__(256) void gemm_kernel(
    const float* __restrict__ A, const float* __restrict__ A2,
    const float* __restrict__ W, const float* __restrict__ bias,
    const float* __restrict__ gamma, const float* __restrict__ beta,
    float* __restrict__ out)
{
    extern __shared__ float sm[];
    constexpr int WROWS = TWO_IN ? 256 : 128;
    float* Ws = sm;
    float* As = sm + WROWS * 128;
    int tid = threadIdx.x;
    for (int i = tid * 4; i < WROWS * 128; i += 1024)
        *(float4*)(Ws + i) = *(const float4*)(W + i);
    int tx = tid & 31, ty = tid >> 5;
    size_t rowBase = (size_t)blockIdx.x * 64;

    float acc[8][4];
    float4 bv = *(const float4*)(bias + tx * 4);
    #pragma unroll
    for (int r = 0; r < 8; r++) { acc[r][0] = bv.x; acc[r][1] = bv.y; acc[r][2] = bv.z; acc[r][3] = bv.w; }

    #pragma unroll
    for (int pass = 0; pass < (TWO_IN ? 2 : 1); pass++) {
        const float* Ain = pass ? A2 : A;
        const float* Wp  = Ws + pass * 128 * 128;
        __syncthreads();
        for (int i = tid * 4; i < 64 * 128; i += 1024)
            *(float4*)(As + i) = *(const float4*)(Ain + rowBase * 128 + i);
        __syncthreads();
        #pragma unroll 4
        for (int k = 0; k < 128; k++) {
            float4 w = *(const float4*)(Wp + k * 128 + tx * 4);
            #pragma unroll
            for (int r = 0; r < 8; r++) {
                float a = As[(ty * 8 + r) * 128 + k];
                acc[r][0] += a * w.x; acc[r][1] += a * w.y;
                acc[r][2] += a * w.z; acc[r][3] += a * w.w;
            }
        }
    }

    if (!DO_LN) {
        #pragma unroll
        for (int r = 0; r < 8; r++) {
            size_t row = rowBase + ty * 8 + r;
            float4 o;
            o.x = gelu_exact(acc[r][0]); o.y = gelu_exact(acc[r][1]);
            o.z = gelu_exact(acc[r][2]); o.w = gelu_exact(acc[r][3]);
            *(float4*)(out + row * 128 + tx * 4) = o;
        }
    } else {
        float4 g4 = *(const float4*)(gamma + tx * 4);
        float4 b4 = *(const float4*)(beta + tx * 4);
        #pragma unroll
        for (int r = 0; r < 8; r++) {
            float s1 = acc[r][0] + acc[r][1] + acc[r][2] + acc[r][3];
            float s2 = acc[r][0]*acc[r][0] + acc[r][1]*acc[r][1]
                     + acc[r][2]*acc[r][2] + acc[r][3]*acc[r][3];
            #pragma unroll
            for (int off = 16; off > 0; off >>= 1) {
                s1 += __shfl_xor_sync(0xffffffffu, s1, off);
                s2 += __shfl_xor_sync(0xffffffffu, s2, off);
            }
            float mu = s1 * (1.0f / 128.0f);
            float var = s2 * (1.0f / 128.0f) - mu * mu;
            float rstd = rsqrtf(var + LN_EPS);
            size_t row = rowBase + ty * 8 + r;
            float4 o;
            o.x = (acc[r][0] - mu) * rstd * g4.x + b4.x;
            o.y = (acc[r][1] - mu) * rstd * g4.y + b4.y;
            o.z = (acc[r][2] - mu) * rstd * g4.z + b4.z;
            o.w = (acc[r][3] - mu) * rstd * g4.w + b4.w;
            *(float4*)(out + row * 128 + tx * 4) = o;
        }
    }
}

// ---------------- launch ----------------
extern "C" void kernel_launch(void* const* d_in, const int* in_sizes, int n_in,
                              void* d_out, int out_size) {
    const float* x      = (const float*)d_in[0];
    const int*   ei     = (const int*)d_in[1];
    const float* pool_p = (const float*)d_in[2];
    const float* dW1 = (const float*)d_in[3];
    const float* db1 = (const float*)d_in[4];
    const float* dW2 = (const float*)d_in[5];
    const float* db2 = (const float*)d_in[6];
    const float* dW3 = (const float*)d_in[7];
    const float* db3 = (const float*)d_in[8];
    const float* dg    = (const float*)d_in[9];
    const float* dbeta = (const float*)d_in[10];
    const float* uW1 = (const float*)d_in[11];
    const float* ub1 = (const float*)d_in[12];
    const float* uW2 = (const float*)d_in[13];
    const float* ub2 = (const float*)d_in[14];
    const float* uW3 = (const float*)d_in[15];
    const float* ub3 = (const float*)d_in[16];
    const float* ug    = (const float*)d_in[17];
    const float* ubeta = (const float*)d_in[18];
    float* out = (float*)d_out;

    const int* senders   = ei;
    const int* receivers = ei + N_EDGES;

    float *B0, *B1, *B2;
    cudaGetSymbolAddress((void**)&B0, g_B0);
    cudaGetSymbolAddress((void**)&B1, g_B1);
    cudaGetSymbolAddress((void**)&B2, g_B2);
    int* degp;
    cudaGetSymbolAddress((void**)&degp, g_deg);

    cudaFuncSetAttribute(gemm_kernel<false, false>, cudaFuncAttributeMaxDynamicSharedMemorySize, 98304);
    cudaFuncSetAttribute(gemm_kernel<false, true >, cudaFuncAttributeMaxDynamicSharedMemorySize, 98304);
    cudaFuncSetAttribute(gemm_kernel<true,  false>, cudaFuncAttributeMaxDynamicSharedMemorySize, 163840);

    // --- CSR build (independent of pooling; issue first) ---
    cudaMemsetAsync(degp, 0, N_NODES * sizeof(int));
    k_count<<<2048, 256>>>(senders, receivers);
    k_scan1<<<256, 512>>>();
    k_scan2<<<1, 256>>>();
    k_scan3<<<256, 512>>>();
    k_scatter<<<2048, 256>>>(senders, receivers);

    // --- pooling scores + exact top-k selection ---
    k_norm<<<1, 128>>>(pool_p);
    k_score<<<N_NODES / 4, 128>>>(x, pool_p);
    k_rinit<<<1, 256>>>();
    for (int sh = 24; sh >= 0; sh -= 8) {
        k_hist<<<256, 256>>>(sh);
        k_rselect<<<1, 1>>>(sh);
    }
    k_eqcount<<<256, 512>>>();
    k_eqscan<<<1, 1>>>();
    k_mark<<<256, 512>>>();

    // --- down conv: gather agg -> B1, MLP -> B0 (= x_d) ---
    k_down_gather<<<N_NODES / 8, 256>>>(x, B1);
    gemm_kernel<false, false><<<K_SEL / 64, 256, 98304>>>(B1, nullptr, dW1, db1, nullptr, nullptr, B2);
    gemm_kernel<false, false><<<K_SEL / 64, 256, 98304>>>(B2, nullptr, dW2, db2, nullptr, nullptr, B1);
    gemm_kernel<false, true ><<<K_SEL / 64, 256, 98304>>>(B1, nullptr, dW3, db3, dg, dbeta, B0);

    // --- up conv: gather agg_skip -> B1, agg_rec -> B2, MLP -> out ---
    k_up_gather<<<N_NODES / 8, 256>>>(x, B0, B1, B2);
    gemm_kernel<true,  false><<<N_NODES / 64, 256, 163840>>>(B2, B1, uW1, ub1, nullptr, nullptr, B0);
    gemm_kernel<false, false><<<N_NODES / 64, 256, 98304>>>(B0, nullptr, uW2, ub2, nullptr, nullptr, B1);
    gemm_kernel<false, true ><<<N_NODES / 64, 256, 98304>>>(B1, nullptr, uW3, ub3, ug, ubeta, out);
}

// round 3
// speedup vs baseline: 1.5199x; 1.0801x over previous
#include <cuda_runtime.h>
#include <cuda_bf16.h>
#include <math.h>

#define N_NODES 131072
#define N_EDGES 524288
#define H_DIM   128
#define K_SEL   (N_NODES / 2)
#define LN_EPS  1e-5f

// ---------------- scratch (static device globals: no allocations allowed) ----------------
__device__ float    g_B0[(size_t)N_NODES * H_DIM];
__device__ float    g_B1[(size_t)N_NODES * H_DIM];
__device__ float    g_B2[(size_t)N_NODES * H_DIM];
__device__ float    g_score[N_NODES];
__device__ float    g_ts[N_NODES];
__device__ unsigned g_key[N_NODES];
__device__ int      g_mapm[N_NODES];     // >=0: compact index if selected, -1 otherwise
__device__ unsigned g_hist[256];
__device__ unsigned g_prefix;
__device__ unsigned g_rem;
__device__ int      g_cnt;
__device__ unsigned g_blkeq[256];
__device__ unsigned g_blkoff[256];
__device__ float    g_invnorm;
// CSR of symmetrized graph
__device__ int      g_deg[N_NODES];
__device__ int      g_rowptr[N_NODES + 1];
__device__ int      g_cur[N_NODES];
__device__ int      g_adj[2 * N_EDGES];
__device__ int      g_tmpscan[N_NODES];
__device__ int      g_bsum[256];

// ---------------- helpers ----------------
__device__ __forceinline__ unsigned sortable_key(float f) {
    unsigned u = __float_as_uint(f);
    return (u & 0x80000000u) ? ~u : (u | 0x80000000u);
}
__device__ __forceinline__ float gelu_exact(float x) {
    return x * normcdff(x);
}
__device__ __forceinline__ unsigned to_tf32(float f) {
    unsigned u;
    asm("cvt.rna.tf32.f32 %0, %1;" : "=r"(u) : "f"(f));
    return u;
}

// ---------------- pool_p norm ----------------
__global__ void k_norm(const float* __restrict__ p) {
    __shared__ float s[128];
    int t = threadIdx.x;
    float v = p[t];
    s[t] = v * v;
    __syncthreads();
    for (int off = 64; off > 0; off >>= 1) {
        if (t < off) s[t] += s[t + off];
        __syncthreads();
    }
    if (t == 0) g_invnorm = rsqrtf(s[0]);
}

// ---------------- scores + keys (warp per row) ----------------
__global__ void k_score(const float* __restrict__ x, const float* __restrict__ p) {
    int row  = blockIdx.x * 4 + (threadIdx.x >> 5);
    int lane = threadIdx.x & 31;
    int c = lane * 4;
    float4 xv = *(const float4*)(x + (size_t)row * H_DIM + c);
    float4 pv = *(const float4*)(p + c);
    float v = xv.x * pv.x + xv.y * pv.y + xv.z * pv.z + xv.w * pv.w;
    #pragma unroll
    for (int off = 16; off > 0; off >>= 1) v += __shfl_xor_sync(0xffffffffu, v, off);
    if (lane == 0) {
        float s = v * g_invnorm;
        g_score[row] = s;
        g_ts[row] = tanhf(s);
        g_key[row] = sortable_key(s);
    }
}

// ---------------- radix select of k-th largest key ----------------
__global__ void k_rinit() {
    int t = threadIdx.x;
    g_hist[t] = 0;
    if (t == 0) { g_prefix = 0; g_rem = K_SEL; g_cnt = 0; }
}
__global__ void k_hist(int shift) {
    __shared__ unsigned h[256];
    int t = threadIdx.x;
    h[t] = 0;
    __syncthreads();
    unsigned pref = g_prefix;
    unsigned hi = (shift == 24) ? 0u : (0xFFFFFFFFu << (shift + 8));
    for (int i = blockIdx.x * blockDim.x + t; i < N_NODES; i += gridDim.x * blockDim.x) {
        unsigned u = g_key[i];
        if ((u & hi) == pref) atomicAdd(&h[(u >> shift) & 255u], 1u);
    }
    __syncthreads();
    if (h[t]) atomicAdd(&g_hist[t], h[t]);
}
__global__ void k_rselect(int shift) {
    unsigned rem = g_rem, pref = g_prefix;
    for (int b = 255; b >= 0; b--) {
        unsigned c = g_hist[b];
        if (c < rem) rem -= c;
        else { pref |= ((unsigned)b) << shift; break; }
    }
    g_prefix = pref;
    g_rem = rem;
    for (int i = 0; i < 256; i++) g_hist[i] = 0;
}

// ---------------- tie-aware selection ----------------
__global__ void k_eqcount() {
    __shared__ unsigned cnt;
    int t = threadIdx.x;
    if (t == 0) cnt = 0;
    __syncthreads();
    int i = blockIdx.x * 512 + t;
    unsigned T = g_prefix;
    if (g_key[i] == T) atomicAdd(&cnt, 1u);
    __syncthreads();
    if (t == 0) g_blkeq[blockIdx.x] = cnt;
}
__global__ void k_eqscan() {
    unsigned run = 0;
    for (int i = 0; i < 256; i++) { g_blkoff[i] = run; run += g_blkeq[i]; }
}
__global__ void k_mark() {
    __shared__ int sb[512];
    int t = threadIdx.x;
    int i = blockIdx.x * 512 + t;
    unsigned T = g_prefix;
    unsigned u = g_key[i];
    int eq = (u == T) ? 1 : 0;
    int gt = (u > T) ? 1 : 0;
    sb[t] = eq;
    __syncthreads();
    for (int off = 1; off < 512; off <<= 1) {
        int v = (t >= off) ? sb[t - off] : 0;
        __syncthreads();
        sb[t] += v;
        __syncthreads();
    }
    int excl = sb[t] - eq;
    int sel = gt || (eq && (g_blkoff[blockIdx.x] + (unsigned)excl) < g_rem);
    g_mapm[i] = sel ? atomicAdd(&g_cnt, 1) : -1;
}

// ---------------- CSR build ----------------
__global__ void k_count(const int* __restrict__ senders, const int* __restrict__ receivers) {
    for (int e = blockIdx.x * blockDim.x + threadIdx.x; e < N_EDGES; e += gridDim.x * blockDim.x) {
        atomicAdd(&g_deg[senders[e]], 1);
        atomicAdd(&g_deg[receivers[e]], 1);
    }
}
__global__ void k_scan1() {
    __shared__ int sb[512];
    int t = threadIdx.x;
    int i = blockIdx.x * 512 + t;
    int v = g_deg[i];
    sb[t] = v;
    __syncthreads();
    for (int off = 1; off < 512; off <<= 1) {
        int a = (t >= off) ? sb[t - off] : 0;
        __syncthreads();
        sb[t] += a;
        __syncthreads();
    }
    g_tmpscan[i] = sb[t];
    if (t == 511) g_bsum[blockIdx.x] = sb[511];
}
__global__ void k_scan2() {
    __shared__ int sb[256];
    int t = threadIdx.x;
    sb[t] = g_bsum[t];
    __syncthreads();
    for (int off = 1; off < 256; off <<= 1) {
        int a = (t >= off) ? sb[t - off] : 0;
        __syncthreads();
        sb[t] += a;
        __syncthreads();
    }
    g_bsum[t] = sb[t];
}
__global__ void k_scan3() {
    int t = threadIdx.x;
    int i = blockIdx.x * 512 + t;
    int off = (blockIdx.x > 0) ? g_bsum[blockIdx.x - 1] : 0;
    int incl = g_tmpscan[i] + off;
    int excl = incl - g_deg[i];
    g_rowptr[i] = excl;
    g_cur[i] = excl;
    if (i == N_NODES - 1) g_rowptr[N_NODES] = incl;
}
__global__ void k_scatter(const int* __restrict__ senders, const int* __restrict__ receivers) {
    for (int e = blockIdx.x * blockDim.x + threadIdx.x; e < N_EDGES; e += gridDim.x * blockDim.x) {
        int s = senders[e], r = receivers[e];
        g_adj[atomicAdd(&g_cur[s], 1)] = r;
        g_adj[atomicAdd(&g_cur[r], 1)] = s;
    }
}

// ---------------- down aggregation: gather (warp per node) ----------------
__global__ void k_down_gather(const float* __restrict__ x, float* __restrict__ out) {
    int v    = blockIdx.x * 8 + (threadIdx.x >> 5);
    int lane = threadIdx.x & 31;
    int mv = g_mapm[v];
    if (mv < 0) return;
    int c = lane * 4;
    int beg = g_rowptr[v], end = g_rowptr[v + 1];
    float4 acc = make_float4(0.f, 0.f, 0.f, 0.f);
    for (int i = beg; i < end; i++) {
        int u = g_adj[i];
        if (g_mapm[u] >= 0) {
            float t = g_ts[u];
            float4 xv = *(const float4*)(x + (size_t)u * H_DIM + c);
            acc.x += xv.x * t; acc.y += xv.y * t;
            acc.z += xv.z * t; acc.w += xv.w * t;
        }
    }
    *(float4*)(out + (size_t)mv * H_DIM + c) = acc;
}

// ---------------- up aggregation: gather (warp per node) ----------------
__global__ void k_up_gather(const float* __restrict__ x, const float* __restrict__ xd,
                            float* __restrict__ agg_skip, float* __restrict__ agg_rec) {
    int v    = blockIdx.x * 8 + (threadIdx.x >> 5);
    int lane = threadIdx.x & 31;
    int c = lane * 4;
    int beg = g_rowptr[v], end = g_rowptr[v + 1];
    float4 as = make_float4(0.f, 0.f, 0.f, 0.f);
    float4 ar = make_float4(0.f, 0.f, 0.f, 0.f);
    for (int i = beg; i < end; i++) {
        int u = g_adj[i];
        float4 xv = *(const float4*)(x + (size_t)u * H_DIM + c);
        as.x += xv.x; as.y += xv.y; as.z += xv.z; as.w += xv.w;
        int mu = g_mapm[u];
        if (mu >= 0) {
            float4 dv = *(const float4*)(xd + (size_t)mu * H_DIM + c);
            ar.x += dv.x; ar.y += dv.y; ar.z += dv.z; ar.w += dv.w;
        }
    }
    *(float4*)(agg_skip + (size_t)v * H_DIM + c) = as;
    *(float4*)(agg_rec  + (size_t)v * H_DIM + c) = ar;
}

// ---------------- tf32 tensor-core GEMM (+bias, +GELU or +LN epilogue) ----------------
// OUT[rows,128] = epi( A@W (+ A2@W2) + bias ). Block: 256 thr = 8 warps.
// Block tile: 128 rows x 128 cols. Warp tile: 16 rows x 128 cols (full row in
// one warp so LN reduces within a 4-lane shfl group). mma.sync.m16n8k8 tf32.
// SMEM: W [WROWS][132] tf32, A [128][132] tf32 (+4 pad => conflict-free frags).
#define SM_STRIDE 132
template<bool TWO_IN, bool DO_LN>
__global__ __launch_bounds__(256) void mma_gemm(
    const float* __restrict__ A, const float* __restrict__ A2,
    const float* __restrict__ W, const float* __restrict__ bias,
    const float* __restrict__ gamma, const float* __restrict__ beta,
    float* __restrict__ out)
{
    extern __shared__ unsigned smu[];
    constexpr int WROWS = TWO_IN ? 256 : 128;
    unsigned* Ws = smu;
    unsigned* As = smu + WROWS * SM_STRIDE;
    int tid = threadIdx.x;

    // stage W (tf32-converted)
    for (int i = tid; i < WROWS * 32; i += 256) {
        int r = i >> 5, c4 = (i & 31) * 4;
        float4 w = *(const float4*)(W + r * 128 + c4);
        uint4 o;
        o.x = to_tf32(w.x); o.y = to_tf32(w.y); o.z = to_tf32(w.z); o.w = to_tf32(w.w);
        *(uint4*)(Ws + r * SM_STRIDE + c4) = o;
    }

    int lane = tid & 31, wid = tid >> 5;
    int g = lane >> 2, t = lane & 3;
    int wm = wid * 16;                       // warp row offset in block tile
    size_t rowBase = (size_t)blockIdx.x * 128;

    float c[16][4];
    #pragma unroll
    for (int j = 0; j < 16; j++) {
        int col = j * 8 + 2 * t;
        float b0 = __ldg(bias + col), b1 = __ldg(bias + col + 1);
        c[j][0] = b0; c[j][1] = b1; c[j][2] = b0; c[j][3] = b1;
    }

    #pragma unroll
    for (int pass = 0; pass < (TWO_IN ? 2 : 1); pass++) {
        const float* Ain = pass ? A2 : A;
        const unsigned* Wp = Ws + pass * 128 * SM_STRIDE;
        __syncthreads();
        for (int i = tid; i < 128 * 32; i += 256) {
            int r = i >> 5, c4 = (i & 31) * 4;
            float4 a = *(const float4*)(Ain + (rowBase + r) * 128 + c4);
            uint4 o;
            o.x = to_tf32(a.x); o.y = to_tf32(a.y); o.z = to_tf32(a.z); o.w = to_tf32(a.w);
            *(uint4*)(As + r * SM_STRIDE + c4) = o;
        }
        __syncthreads();
        #pragma unroll
        for (int kt = 0; kt < 16; kt++) {
            int k0 = kt * 8;
            unsigned a0 = As[(wm + g)     * SM_STRIDE + k0 + t];
            unsigned a1 = As[(wm + g + 8) * SM_STRIDE + k0 + t];
            unsigned a2 = As[(wm + g)     * SM_STRIDE + k0 + t + 4];
            unsigned a3 = As[(wm + g + 8) * SM_STRIDE + k0 + t + 4];
            #pragma unroll
            for (int j = 0; j < 16; j++) {
                unsigned b0 = Wp[(k0 + t)     * SM_STRIDE + j * 8 + g];
                unsigned b1 = Wp[(k0 + t + 4) * SM_STRIDE + j * 8 + g];
                asm volatile(
                    "mma.sync.aligned.m16n8k8.row.col.f32.tf32.tf32.f32 "
                    "{%0,%1,%2,%3},{%4,%5,%6,%7},{%8,%9},{%0,%1,%2,%3};"
                    : "+f"(c[j][0]), "+f"(c[j][1]), "+f"(c[j][2]), "+f"(c[j][3])
                    : "r"(a0), "r"(a1), "r"(a2), "r"(a3), "r"(b0), "r"(b1));
            }
        }
    }

    size_t rA = rowBase + wm + g;       // row for c[j][0..1]
    size_t rB = rA + 8;                 // row for c[j][2..3]

    if (!DO_LN) {
        #pragma unroll
        for (int j = 0; j < 16; j++) {
            int col = j * 8 + 2 * t;
            float2 oA = make_float2(gelu_exact(c[j][0]), gelu_exact(c[j][1]));
            float2 oB = make_float2(gelu_exact(c[j][2]), gelu_exact(c[j][3]));
            *(float2*)(out + rA * 128 + col) = oA;
            *(float2*)(out + rB * 128 + col) = oB;
        }
    } else {
        float s1a = 0.f, s2a = 0.f, s1b = 0.f, s2b = 0.f;
        #pragma unroll
        for (int j = 0; j < 16; j++) {
            s1a += c[j][0] + c[j][1];
            s2a += c[j][0] * c[j][0] + c[j][1] * c[j][1];
            s1b += c[j][2] + c[j][3];
            s2b += c[j][2] * c[j][2] + c[j][3] * c[j][3];
        }
        #pragma unroll
        for (int off = 1; off <= 2; off <<= 1) {
            s1a += __shfl_xor_sync(0xffffffffu, s1a, off);
            s2a += __shfl_xor_sync(0xffffffffu, s2a, off);
            s1b += __shfl_xor_sync(0xffffffffu, s1b, off);
            s2b += __shfl_xor_sync(0xffffffffu, s2b, off);
        }
        float muA = s1a * (1.0f / 128.0f);
        float muB = s1b * (1.0f / 128.0f);
        float rsA = rsqrtf(s2a * (1.0f / 128.0f) - muA * muA + LN_EPS);
        float rsB = rsqrtf(s2b * (1.0f / 128.0f) - muB * muB + LN_EPS);
        #pragma unroll
        for (int j = 0; j < 16; j++) {
            int col = j * 8 + 2 * t;
            float g0 = __ldg(gamma + col), g1 = __ldg(gamma + col + 1);
            float be0 = __ldg(beta + col), be1 = __ldg(beta + col + 1);
            float2 oA = make_float2((c[j][0] - muA) * rsA * g0 + be0,
                                    (c[j][1] - muA) * rsA * g1 + be1);
            float2 oB = make_float2((c[j][2] - muB) * rsB * g0 + be0,
                                    (c[j][3] - muB) * rsB * g1 + be1);
            *(float2*)(out + rA * 128 + col) = oA;
            *(float2*)(out + rB * 128 + col) = oB;
        }
    }
}

#define SMEM_1IN ((128 * SM_STRIDE + 128 * SM_STRIDE) * 4)
#define SMEM_2IN ((256 * SM_STRIDE + 128 * SM_STRIDE) * 4)

// ---------------- launch ----------------
extern "C" void kernel_launch(void* const* d_in, const int* in_sizes, int n_in,
                              void* d_out, int out_size) {
    const float* x      = (const float*)d_in[0];
    const int*   ei     = (const int*)d_in[1];
    const float* pool_p = (const float*)d_in[2];
    const float* dW1 = (const float*)d_in[3];
    const float* db1 = (const float*)d_in[4];
    const float* dW2 = (const float*)d_in[5];
    const float* db2 = (const float*)d_in[6];
    const float* dW3 = (const float*)d_in[7];
    const float* db3 = (const float*)d_in[8];
    const float* dg    = (const float*)d_in[9];
    const float* dbeta = (const float*)d_in[10];
    const float* uW1 = (const float*)d_in[11];
    const float* ub1 = (const float*)d_in[12];
    const float* uW2 = (const float*)d_in[13];
    const float* ub2 = (const float*)d_in[14];
    const float* uW3 = (const float*)d_in[15];
    const float* ub3 = (const float*)d_in[16];
    const float* ug    = (const float*)d_in[17];
    const float* ubeta = (const float*)d_in[18];
    float* out = (float*)d_out;

    const int* senders   = ei;
    const int* receivers = ei + N_EDGES;

    float *B0, *B1, *B2;
    cudaGetSymbolAddress((void**)&B0, g_B0);
    cudaGetSymbolAddress((void**)&B1, g_B1);
    cudaGetSymbolAddress((void**)&B2, g_B2);
    int* degp;
    cudaGetSymbolAddress((void**)&degp, g_deg);

    cudaFuncSetAttribute(mma_gemm<false, false>, cudaFuncAttributeMaxDynamicSharedMemorySize, SMEM_1IN);
    cudaFuncSetAttribute(mma_gemm<false, true >, cudaFuncAttributeMaxDynamicSharedMemorySize, SMEM_1IN);
    cudaFuncSetAttribute(mma_gemm<true,  false>, cudaFuncAttributeMaxDynamicSharedMemorySize, SMEM_2IN);

    // --- CSR build (independent of pooling; issue first) ---
    cudaMemsetAsync(degp, 0, N_NODES * sizeof(int));
    k_count<<<2048, 256>>>(senders, receivers);
    k_scan1<<<256, 512>>>();
    k_scan2<<<1, 256>>>();
    k_scan3<<<256, 512>>>();
    k_scatter<<<2048, 256>>>(senders, receivers);

    // --- pooling scores + exact top-k selection ---
    k_norm<<<1, 128>>>(pool_p);
    k_score<<<N_NODES / 4, 128>>>(x, pool_p);
    k_rinit<<<1, 256>>>();
    for (int sh = 24; sh >= 0; sh -= 8) {
        k_hist<<<256, 256>>>(sh);
        k_rselect<<<1, 1>>>(sh);
    }
    k_eqcount<<<256, 512>>>();
    k_eqscan<<<1, 1>>>();
    k_mark<<<256, 512>>>();

    // --- down conv: gather agg -> B1, MLP -> B0 (= x_d) ---
    k_down_gather<<<N_NODES / 8, 256>>>(x, B1);
    mma_gemm<false, false><<<K_SEL / 128, 256, SMEM_1IN>>>(B1, nullptr, dW1, db1, nullptr, nullptr, B2);
    mma_gemm<false, false><<<K_SEL / 128, 256, SMEM_1IN>>>(B2, nullptr, dW2, db2, nullptr, nullptr, B1);
    mma_gemm<false, true ><<<K_SEL / 128, 256, SMEM_1IN>>>(B1, nullptr, dW3, db3, dg, dbeta, B0);

    // --- up conv: gather agg_skip -> B1, agg_rec -> B2, MLP -> out ---
    k_up_gather<<<N_NODES / 8, 256>>>(x, B0, B1, B2);
    mma_gemm<true,  false><<<N_NODES / 128, 256, SMEM_2IN>>>(B2, B1, uW1, ub1, nullptr, nullptr, B0);
    mma_gemm<false, false><<<N_NODES / 128, 256, SMEM_1IN>>>(B0, nullptr, uW2, ub2, nullptr, nullptr, B1);
    mma_gemm<false, true ><<<N_NODES / 128, 256, SMEM_1IN>>>(B1, nullptr, uW3, ub3, ug, ubeta, out);
}